// round 6
// baseline (speedup 1.0000x reference)
#include <cuda_runtime.h>
#include <cuda_bf16.h>
#include <math_constants.h>

#define NB   16
#define NP   4096
#define SS   1024
#define KK   64
#define CIN  64
#define NC   (NB*SS)   /* 16384 centers */
#define NWORK 132      /* worker blocks */
#define NTILE 2048     /* 8-center tiles */
#define SPIN_GUARD (1<<24)

typedef unsigned short ushort_t;
typedef unsigned int   uint_t;
typedef unsigned long long ull_t;

// ---------------- scratch (static device globals; no allocation) ----------------
__device__ int g_fps[NC];
__device__ int g_nbr[NC*KK];
__device__ int g_cnt[NC];
__device__ int g_prog[NB];
__device__ int g_done;
__device__ ushort_t g_xh[(size_t)NB*NP*CIN];   // pre-split x, hi bf16
__device__ ushort_t g_xl[(size_t)NB*NP*CIN];   // pre-split x, lo bf16

// Reference-matching squared distance: no FMA contraction, sum order (x+y)+z.
__device__ __forceinline__ float d2_ref(float dx, float dy, float dz) {
    return __fadd_rn(__fadd_rn(__fmul_rn(dx,dx), __fmul_rn(dy,dy)), __fmul_rn(dz,dz));
}

__device__ __forceinline__ void split_one(float v, ushort_t& h, ushort_t& l) {
    __nv_bfloat16 hb = __float2bfloat16(v);
    __nv_bfloat16 lb = __float2bfloat16(v - __bfloat162float(hb));
    h = __bfloat16_as_ushort(hb); l = __bfloat16_as_ushort(lb);
}
__device__ __forceinline__ void split_pack2(float a, float b, uint_t& h, uint_t& l) {
    ushort_t ha, la, hb, lb;
    split_one(a, ha, la); split_one(b, hb, lb);
    h = (uint_t)ha | ((uint_t)hb << 16);
    l = (uint_t)la | ((uint_t)lb << 16);
}
__device__ __forceinline__ void mma16816(float* c, uint_t a0,uint_t a1,uint_t a2,uint_t a3,
                                         uint_t b0, uint_t b1) {
    asm volatile("mma.sync.aligned.m16n8k16.row.col.f32.bf16.bf16.f32 "
        "{%0,%1,%2,%3}, {%4,%5,%6,%7}, {%8,%9}, {%0,%1,%2,%3};"
        : "+f"(c[0]),"+f"(c[1]),"+f"(c[2]),"+f"(c[3])
        : "r"(a0),"r"(a1),"r"(a2),"r"(a3),"r"(b0),"r"(b1));
}

// =====================================================================
// init: reset cross-launch state (tiny, runs before fused kernel)
// =====================================================================
__global__ void init_kernel()
{
    if (threadIdx.x < NB) g_prog[threadIdx.x] = -1;
    if (threadIdx.x == 0) g_done = 0;
}

// =====================================================================
// smem layout (byte offsets) — worker path
// =====================================================================
#define O_BIAS 0
#define O_BH   1024
#define O_BL   35840
#define O_A1H  70656
#define O_A1L  111616
#define O_A2H  152576
#define O_A2L  185344
#define O_RED  218112
#define SMEM_TOTAL 222208
#define SLOT_L1 0
#define SLOT_L2 40
#define SLOT_L3 72

template<int KS, int NTL>
__device__ __forceinline__ void mm_packed(
    const unsigned char* sp, int awh, int awl, int slotbase, int ntofs,
    const float* __restrict__ bsl, float acc[8][4], int lane)
{
    const int tig = lane & 3;
    #pragma unroll
    for (int nt = 0; nt < 8; nt++) {
        const int c0 = nt*8 + tig*2;
        acc[nt][0] = bsl[c0]; acc[nt][1] = bsl[c0+1];
        acc[nt][2] = acc[nt][0]; acc[nt][3] = acc[nt][1];
    }
    const uint2* BH = (const uint2*)(sp + O_BH);
    const uint2* BL = (const uint2*)(sp + O_BL);
    #pragma unroll
    for (int ks = 0; ks < KS; ks++) {
        const uint4 Ah = *(const uint4*)(sp + awh + ks*512 + lane*16);
        const uint4 Al = *(const uint4*)(sp + awl + ks*512 + lane*16);
        #pragma unroll
        for (int nt = 0; nt < 8; nt++) {
            const int slot = (slotbase + ks*NTL + ntofs + nt)*32 + lane;
            const uint2 bh = BH[slot];
            const uint2 bl = BL[slot];
            mma16816(acc[nt], Ah.x,Ah.y,Ah.z,Ah.w, bh.x,bh.y);
            mma16816(acc[nt], Ah.x,Ah.y,Ah.z,Ah.w, bl.x,bl.y);
            mma16816(acc[nt], Al.x,Al.y,Al.z,Al.w, bh.x,bh.y);
        }
    }
}

__device__ __forceinline__ void epi_relu_pack(
    unsigned char* sp, int a2h, int a2l, float acc[8][4], int lane)
{
    #pragma unroll
    for (int ks = 0; ks < 4; ks++) {
        uint4 H, L;
        split_pack2(fmaxf(acc[2*ks][0],0.f),   fmaxf(acc[2*ks][1],0.f),   H.x, L.x);
        split_pack2(fmaxf(acc[2*ks][2],0.f),   fmaxf(acc[2*ks][3],0.f),   H.y, L.y);
        split_pack2(fmaxf(acc[2*ks+1][0],0.f), fmaxf(acc[2*ks+1][1],0.f), H.z, L.z);
        split_pack2(fmaxf(acc[2*ks+1][2],0.f), fmaxf(acc[2*ks+1][3],0.f), H.w, L.w);
        *(uint4*)(sp + a2h + ks*512 + lane*16) = H;
        *(uint4*)(sp + a2l + ks*512 + lane*16) = L;
    }
}

// =====================================================================
// FPS path (blocks 0-15). Bitwise-identical picks to reference.
// One barrier per iteration: warp reduce -> shared atomicMax into a
// 3-slot rotating u64 cell; progress published every 4 iterations.
// =====================================================================
__device__ void fps_path(const float* __restrict__ pos, ull_t* S)
{
    const int b = blockIdx.x;
    const float* p = pos + (size_t)b * NP * 3;
    const int tid = threadIdx.x;
    const int i0 = tid * 8;

    float px[8], py[8], pz[8], dmin[8];
    #pragma unroll
    for (int j = 0; j < 8; j++) {
        px[j] = p[3*(i0+j)+0];
        py[j] = p[3*(i0+j)+1];
        pz[j] = p[3*(i0+j)+2];
        dmin[j] = CUDART_INF_F;
    }

    if (tid == 0) {
        S[0] = S[1] = S[2] = 0;
        g_fps[b*SS] = 0;
        __threadfence();
        *(volatile int*)&g_prog[b] = 0;
    }
    __syncthreads();

    int cur = 0;
    const int lane = tid & 31;
    for (int t = 1; t < SS; t++) {
        const float cx = p[3*cur], cy = p[3*cur+1], cz = p[3*cur+2];

        #pragma unroll
        for (int j = 0; j < 8; j++)
            dmin[j] = fminf(dmin[j], d2_ref(px[j]-cx, py[j]-cy, pz[j]-cz));

        // max via tree (values only), then first index with equality
        float m01 = fmaxf(dmin[0], dmin[1]), m23 = fmaxf(dmin[2], dmin[3]);
        float m45 = fmaxf(dmin[4], dmin[5]), m67 = fmaxf(dmin[6], dmin[7]);
        float bv  = fmaxf(fmaxf(m01, m23), fmaxf(m45, m67));
        int bi = i0;
        #pragma unroll
        for (int j = 7; j >= 0; j--)
            if (dmin[j] == bv) bi = i0 + j;   // last assignment = smallest j

        // warp reduce (max value, min index on tie)
        #pragma unroll
        for (int o = 16; o > 0; o >>= 1) {
            float v2 = __shfl_down_sync(0xffffffffu, bv, o);
            int   i2 = __shfl_down_sync(0xffffffffu, bi, o);
            if (v2 > bv || (v2 == bv && i2 < bi)) { bv = v2; bi = i2; }
        }
        if (lane == 0)
            atomicMax(&S[t % 3], ((ull_t)__float_as_uint(bv) << 32)
                                 | (ull_t)(0xFFFFFFFFu - (uint_t)bi));
        if (tid == 0) S[(t + 1) % 3] = 0;
        __syncthreads();

        const ull_t key = S[t % 3];
        cur = (int)(0xFFFFFFFFu - (uint_t)(key & 0xFFFFFFFFull));
        if (tid == 0) {
            g_fps[b*SS + t] = cur;
            if ((t & 3) == 3 || t == SS-1) {
                __threadfence();
                *(volatile int*)&g_prog[b] = t;
            }
        }
    }
}

// =====================================================================
// Fused kernel: blocks 0-15 FPS; blocks 16-147 presplit + ballq + MLP.
// =====================================================================
__global__ __launch_bounds__(512, 1) void fused_kernel(
    const float* __restrict__ x, const float* __restrict__ pos,
    const float* __restrict__ W1, const float* __restrict__ b1,
    const float* __restrict__ W2, const float* __restrict__ b2,
    const float* __restrict__ W3, const float* __restrict__ b3,
    float* __restrict__ out, long long out_size)
{
    extern __shared__ unsigned char sp[];
    const int tid = threadIdx.x;

    if (blockIdx.x < NB) {
        fps_path(pos, (ull_t*)sp);
        return;
    }

    // ------------------- worker block -------------------
    const int wb = blockIdx.x - NB;

    // presplit x chunk (strided over workers)
    {
        const int N4 = NB*NP*CIN/4;
        const float4* x4 = (const float4*)x;
        uint2* xh2 = (uint2*)g_xh;
        uint2* xl2 = (uint2*)g_xl;
        for (int i = wb*512 + tid; i < N4; i += NWORK*512) {
            float4 v = x4[i];
            ushort_t h0,l0,h1,l1,h2,l2,h3,l3;
            split_one(v.x,h0,l0); split_one(v.y,h1,l1);
            split_one(v.z,h2,l2); split_one(v.w,h3,l3);
            xh2[i] = make_uint2((uint_t)h0|((uint_t)h1<<16), (uint_t)h2|((uint_t)h3<<16));
            xl2[i] = make_uint2((uint_t)l0|((uint_t)l1<<16), (uint_t)l2|((uint_t)l3<<16));
        }
        __syncthreads();
        if (tid == 0) { __threadfence(); atomicAdd(&g_done, 1); }
    }

    float* bs = (float*)(sp + O_BIAS);

    // pack weights into fragment order (once per block)
    for (int i = tid; i < 136*32; i += 512) {
        const int s = i >> 5, l = i & 31;
        int ks, nt, layer;
        if (s < 40)      { layer = 1; ks = s >> 3;        nt = s & 7; }
        else if (s < 72) { layer = 2; ks = (s-40) >> 3;   nt = (s-40) & 7; }
        else             { layer = 3; ks = (s-72) >> 4;   nt = (s-72) & 15; }
        const int n  = nt*8 + (l >> 2);
        const int k0 = ks*16 + (l & 3)*2;
        float v[4];
        #pragma unroll
        for (int q = 0; q < 4; q++) {
            const int k = k0 + (q >> 1)*8 + (q & 1);
            if (layer == 1)      v[q] = (k < 67) ? W1[k*64 + n]  : 0.f;
            else if (layer == 2) v[q] = W2[k*64 + n];
            else                 v[q] = W3[k*128 + n];
        }
        uint2 H, L;
        split_pack2(v[0], v[1], H.x, L.x);
        split_pack2(v[2], v[3], H.y, L.y);
        ((uint2*)(sp + O_BH))[i] = H;
        ((uint2*)(sp + O_BL))[i] = L;
    }
    if (tid < 64)  { bs[tid] = b1[tid]; bs[64+tid] = b2[tid]; }
    if (tid < 128) { bs[128+tid] = b3[tid]; }
    __syncthreads();

    const int wid   = tid >> 5;
    const int lane  = tid & 31;
    const int team  = tid >> 7;
    const int t128  = tid & 127;
    const int wteam = t128 >> 5;
    const int g4    = lane >> 2;
    const int barid = team + 1;

    const int a1h_t = O_A1H + team*10240;
    const int a1l_t = O_A1L + team*10240;
    const int awh1  = a1h_t + wteam*2560;
    const int awl1  = a1l_t + wteam*2560;
    const int awh2  = O_A2H + team*8192 + wteam*2048;
    const int awl2  = O_A2L + team*8192 + wteam*2048;
    float* tred = (float*)(sp + O_RED) + team*256;

    ull_t* bqbuf = (ull_t*)(sp + O_A1H);         // 8 warps x 256 = 16KB (aliased)
    int*   scnt  = (int*)(sp + O_RED);           // aliased, phase-separated

    // wait for presplit completion (cheap; overlaps with first FPS iters)
    if (tid == 0) {
        volatile int* vd = &g_done;
        int guard = 0;
        while (*vd < NWORK && guard++ < SPIN_GUARD) __nanosleep(128);
        __threadfence();
    }
    __syncthreads();

    float acc[8][4];

    for (int tile = wb; tile < NTILE; tile += NWORK) {
        const int cloudb = tile >> 7;                 // 128 tiles per cloud
        const int t_need = ((tile & 127) << 3) + 7;

        // ---- gate on FPS progress ----
        if (tid == 0) {
            volatile int* vp = &g_prog[cloudb];
            int guard = 0;
            while (*vp < t_need && guard++ < SPIN_GUARD) __nanosleep(128);
            __threadfence();
        }
        __syncthreads();   // separates previous MLP's A-region use from ballq bufs

        // ---- ballq phase: warps 0-7, one center each ----
        if (wid < 8) {
            const int g = tile*8 + wid;
            const float* p = pos + (size_t)cloudb * NP * 3;
            const int ci = g_fps[g];
            const float cx = p[3*ci], cy = p[3*ci+1], cz = p[3*ci+2];
            ull_t* buf = bqbuf + wid*256;

            if (lane == 0) scnt[wid] = 0;
            __syncwarp();

            for (int i = lane; i < NP; i += 32) {
                float d = d2_ref(cx - p[3*i], cy - p[3*i+1], cz - p[3*i+2]);
                if (d <= 0.04f) {
                    int pp = atomicAdd(&scnt[wid], 1);
                    if (pp < 256)
                        buf[pp] = ((ull_t)__float_as_uint(d) << 32) | (uint_t)i;
                }
            }
            __syncwarp();
            const int m = min(scnt[wid], 256);

            if (m > KK) {
                const int n2 = (m <= 128) ? 128 : 256;
                for (int i = m + lane; i < n2; i += 32) buf[i] = ~0ull;
                __syncwarp();
                for (int k = 2; k <= n2; k <<= 1) {
                    for (int j = k >> 1; j > 0; j >>= 1) {
                        for (int i = lane; i < n2; i += 32) {
                            int ixj = i ^ j;
                            if (ixj > i) {
                                ull_t a = buf[i], c = buf[ixj];
                                bool up = ((i & k) == 0);
                                if ((a > c) == up) { buf[i] = c; buf[ixj] = a; }
                            }
                        }
                        __syncwarp();
                    }
                }
            }
            __syncwarp();

            const int n = min(m, KK);
            if (lane == 0) g_cnt[g] = n;
            for (int t = lane; t < KK; t += 32) {
                ull_t e = buf[(t < n) ? t : 0];
                g_nbr[g*KK + t] = (int)(e & 0xffffffffu);
            }

            // fused tail: pos_out + batch_out
            if (lane == 0) {
                const long long base = (long long)NC * 128;
                if (base + (long long)NC * 3 <= out_size) {
                    out[base + g*3 + 0] = cx;
                    out[base + g*3 + 1] = cy;
                    out[base + g*3 + 2] = cz;
                }
                const long long base2 = base + (long long)NC * 3;
                const long long rem = out_size - base2;
                if (rem >= (long long)NC * 2) {
                    ((long long*)(out + base2))[g] = (long long)cloudb;
                } else if (rem >= (long long)NC) {
                    out[base2 + g] = (float)cloudb;
                }
            }
        }
        __syncthreads();   // all bqbuf reads done

        // ---- re-zero ks=4 padding blocks (clobbered by bqbuf aliasing) ----
        // 4 teams x 4 warps x {H,L} x 512B = 16KB; dedicated phase, no overlap
        for (int i = tid; i < 1024; i += 512) {
            const int tm = i >> 8, w = (i >> 6) & 3, hl = (i >> 5) & 1, l = i & 31;
            const int base = (hl ? O_A1L : O_A1H) + tm*10240 + w*2560 + 4*512 + l*16;
            *(uint4*)(sp + base) = make_uint4(0,0,0,0);
        }
        __syncthreads();   // zeros visible before gather writes rel-pos

        // ---- MLP phase: 4 teams x 2 rounds = 8 centers ----
        #pragma unroll 1
        for (int r = 0; r < 2; r++) {
            const int g = tile*8 + team*2 + r;
            const float* p = pos + (size_t)cloudb * NP * 3;
            const int ci = g_fps[g];
            const int ncnt = g_cnt[g];

            // gather into fragment-packed A1
            {
                const int rr = t128 >> 1, half = t128 & 1;
                const int idx = g_nbr[g*KK + rr];
                const size_t row = (size_t)(cloudb*NP + idx);
                const uint4* xh4 = (const uint4*)(g_xh + row*CIN);
                const uint4* xl4 = (const uint4*)(g_xl + row*CIN);
                const int dw   = rr >> 4;
                const int lb   = 4*(rr & 7);
                const int rhi  = ((rr & 15) >= 8) ? 1 : 0;
                const int bh_w = a1h_t + dw*2560;
                const int bl_w = a1l_t + dw*2560;
                #pragma unroll
                for (int q = 0; q < 4; q++) {
                    const uint4 vh = xh4[4*half + q];
                    const uint4 vl = xl4[4*half + q];
                    const int ks  = 2*half + (q >> 1);
                    const int reg = ((q & 1) << 1) + rhi;
                    const int bh  = bh_w + ks*512 + reg*4;
                    const int bl  = bl_w + ks*512 + reg*4;
                    *(uint_t*)(sp + bh + (lb+0)*16) = vh.x;
                    *(uint_t*)(sp + bh + (lb+1)*16) = vh.y;
                    *(uint_t*)(sp + bh + (lb+2)*16) = vh.z;
                    *(uint_t*)(sp + bh + (lb+3)*16) = vh.w;
                    *(uint_t*)(sp + bl + (lb+0)*16) = vl.x;
                    *(uint_t*)(sp + bl + (lb+1)*16) = vl.y;
                    *(uint_t*)(sp + bl + (lb+2)*16) = vl.z;
                    *(uint_t*)(sp + bl + (lb+3)*16) = vl.w;
                }
                // ks=4 block: rel-pos only (padding pre-zeroed above; round r
                // overwrites the same two slots each time -> no race, no staleness)
                if (half == 0) {
                    const float rx = p[3*idx]   - p[3*ci];
                    const float ry = p[3*idx+1] - p[3*ci+1];
                    const float rz = p[3*idx+2] - p[3*ci+2];
                    uint_t h0,l0,h1,l1;
                    split_pack2(rx, ry, h0, l0);
                    split_pack2(rz, 0.f, h1, l1);
                    const int bh = bh_w + 4*512 + rhi*4;
                    const int bl = bl_w + 4*512 + rhi*4;
                    *(uint_t*)(sp + bh + (lb+0)*16) = h0;
                    *(uint_t*)(sp + bh + (lb+1)*16) = h1;
                    *(uint_t*)(sp + bl + (lb+0)*16) = l0;
                    *(uint_t*)(sp + bl + (lb+1)*16) = l1;
                }
            }
            asm volatile("bar.sync %0, %1;" :: "r"(barid), "r"(128));

            // layer 1
            mm_packed<5,8>(sp, awh1, awl1, SLOT_L1, 0, bs, acc, lane);
            epi_relu_pack(sp, awh2, awl2, acc, lane);
            asm volatile("bar.sync %0, %1;" :: "r"(barid), "r"(128));

            // layer 2 (in place)
            mm_packed<4,8>(sp, awh2, awl2, SLOT_L2, 0, bs+64, acc, lane);
            asm volatile("bar.sync %0, %1;" :: "r"(barid), "r"(128));
            epi_relu_pack(sp, awh2, awl2, acc, lane);
            asm volatile("bar.sync %0, %1;" :: "r"(barid), "r"(128));

            // layer 3 + masked column max
            const bool v0 = g4     < ncnt - wteam*16;
            const bool v1 = g4 + 8 < ncnt - wteam*16;
            #pragma unroll
            for (int h = 0; h < 2; h++) {
                mm_packed<4,16>(sp, awh2, awl2, SLOT_L3, h*8, bs+128+h*64, acc, lane);
                #pragma unroll
                for (int nt = 0; nt < 8; nt++) {
                    float m0 = fmaxf(v0 ? acc[nt][0] : -CUDART_INF_F,
                                     v1 ? acc[nt][2] : -CUDART_INF_F);
                    float m1 = fmaxf(v0 ? acc[nt][1] : -CUDART_INF_F,
                                     v1 ? acc[nt][3] : -CUDART_INF_F);
                    #pragma unroll
                    for (int off = 4; off < 32; off <<= 1) {
                        m0 = fmaxf(m0, __shfl_xor_sync(0xffffffffu, m0, off));
                        m1 = fmaxf(m1, __shfl_xor_sync(0xffffffffu, m1, off));
                    }
                    if (lane < 4) {
                        tred[wteam*64 + nt*8 + lane*2    ] = m0;
                        tred[wteam*64 + nt*8 + lane*2 + 1] = m1;
                    }
                }
                asm volatile("bar.sync %0, %1;" :: "r"(barid), "r"(128));
                if (t128 < 64) {
                    float m = fmaxf(fmaxf(tred[t128], tred[64+t128]),
                                    fmaxf(tred[128+t128], tred[192+t128]));
                    out[(size_t)g*128 + h*64 + t128] = m;
                }
                asm volatile("bar.sync %0, %1;" :: "r"(barid), "r"(128));
            }
        }
    }
}

// =====================================================================
extern "C" void kernel_launch(void* const* d_in, const int* in_sizes, int n_in,
                              void* d_out, int out_size)
{
    const float* x   = (const float*)d_in[0];
    const float* pos = (const float*)d_in[1];
    const float* W1 = (const float*)d_in[3];
    const float* b1 = (const float*)d_in[4];
    const float* W2 = (const float*)d_in[5];
    const float* b2 = (const float*)d_in[6];
    const float* W3 = (const float*)d_in[7];
    const float* b3 = (const float*)d_in[8];
    float* out = (float*)d_out;

    cudaFuncSetAttribute(fused_kernel, cudaFuncAttributeMaxDynamicSharedMemorySize, SMEM_TOTAL);

    init_kernel<<<1, 32>>>();
    fused_kernel<<<148, 512, SMEM_TOTAL>>>(x, pos, W1, b1, W2, b2, W3, b3,
                                           out, (long long)out_size);
}

// round 8
// speedup vs baseline: 1.0867x; 1.0867x over previous
#include <cuda_runtime.h>
#include <cuda_bf16.h>
#include <math_constants.h>

#define NB   16
#define NP   4096
#define SS   1024
#define KK   64
#define CIN  64
#define NC   (NB*SS)   /* 16384 centers */
#define NWORK 132      /* worker blocks */
#define NTILE 2048     /* 8-center tasks */
#define SPIN_GUARD (1<<24)

typedef unsigned short ushort_t;
typedef unsigned int   uint_t;
typedef unsigned long long ull_t;

// ---------------- scratch (static device globals; no allocation) ----------------
__device__ int g_fps[NC];
__device__ int g_nbr[NC*KK];
__device__ int g_cnt[NC];
__device__ int g_prog[NB];
__device__ int g_done;
__device__ ushort_t g_xh[(size_t)NB*NP*CIN];   // pre-split x, hi bf16
__device__ ushort_t g_xl[(size_t)NB*NP*CIN];   // pre-split x, lo bf16

// Reference-matching squared distance: no FMA contraction, sum order (x+y)+z.
__device__ __forceinline__ float d2_ref(float dx, float dy, float dz) {
    return __fadd_rn(__fadd_rn(__fmul_rn(dx,dx), __fmul_rn(dy,dy)), __fmul_rn(dz,dz));
}

__device__ __forceinline__ void split_one(float v, ushort_t& h, ushort_t& l) {
    __nv_bfloat16 hb = __float2bfloat16(v);
    __nv_bfloat16 lb = __float2bfloat16(v - __bfloat162float(hb));
    h = __bfloat16_as_ushort(hb); l = __bfloat16_as_ushort(lb);
}
__device__ __forceinline__ void split_pack2(float a, float b, uint_t& h, uint_t& l) {
    ushort_t ha, la, hb, lb;
    split_one(a, ha, la); split_one(b, hb, lb);
    h = (uint_t)ha | ((uint_t)hb << 16);
    l = (uint_t)la | ((uint_t)lb << 16);
}
__device__ __forceinline__ void mma16816(float* c, uint_t a0,uint_t a1,uint_t a2,uint_t a3,
                                         uint_t b0, uint_t b1) {
    asm volatile("mma.sync.aligned.m16n8k16.row.col.f32.bf16.bf16.f32 "
        "{%0,%1,%2,%3}, {%4,%5,%6,%7}, {%8,%9}, {%0,%1,%2,%3};"
        : "+f"(c[0]),"+f"(c[1]),"+f"(c[2]),"+f"(c[3])
        : "r"(a0),"r"(a1),"r"(a2),"r"(a3),"r"(b0),"r"(b1));
}

// =====================================================================
// init: reset cross-launch state (tiny, runs before fused kernel)
// =====================================================================
__global__ void init_kernel()
{
    if (threadIdx.x < NB) g_prog[threadIdx.x] = -1;
    if (threadIdx.x == 0) g_done = 0;
}

// =====================================================================
// smem layout (byte offsets) — worker path
// =====================================================================
#define O_BIAS 0
#define O_BH   1024
#define O_BL   35840
#define O_A1H  70656
#define O_A1L  111616
#define O_A2H  152576
#define O_A2L  185344
#define O_RED  218112
#define SMEM_TOTAL 222208
#define SLOT_L1 0
#define SLOT_L2 40
#define SLOT_L3 72

template<int KS, int NTL>
__device__ __forceinline__ void mm_packed(
    const unsigned char* sp, int awh, int awl, int slotbase, int ntofs,
    const float* __restrict__ bsl, float acc[8][4], int lane)
{
    const int tig = lane & 3;
    #pragma unroll
    for (int nt = 0; nt < 8; nt++) {
        const int c0 = nt*8 + tig*2;
        acc[nt][0] = bsl[c0]; acc[nt][1] = bsl[c0+1];
        acc[nt][2] = acc[nt][0]; acc[nt][3] = acc[nt][1];
    }
    const uint2* BH = (const uint2*)(sp + O_BH);
    const uint2* BL = (const uint2*)(sp + O_BL);
    #pragma unroll
    for (int ks = 0; ks < KS; ks++) {
        const uint4 Ah = *(const uint4*)(sp + awh + ks*512 + lane*16);
        const uint4 Al = *(const uint4*)(sp + awl + ks*512 + lane*16);
        #pragma unroll
        for (int nt = 0; nt < 8; nt++) {
            const int slot = (slotbase + ks*NTL + ntofs + nt)*32 + lane;
            const uint2 bh = BH[slot];
            const uint2 bl = BL[slot];
            mma16816(acc[nt], Ah.x,Ah.y,Ah.z,Ah.w, bh.x,bh.y);
            mma16816(acc[nt], Ah.x,Ah.y,Ah.z,Ah.w, bl.x,bl.y);
            mma16816(acc[nt], Al.x,Al.y,Al.z,Al.w, bh.x,bh.y);
        }
    }
}

__device__ __forceinline__ void epi_relu_pack(
    unsigned char* sp, int a2h, int a2l, float acc[8][4], int lane)
{
    #pragma unroll
    for (int ks = 0; ks < 4; ks++) {
        uint4 H, L;
        split_pack2(fmaxf(acc[2*ks][0],0.f),   fmaxf(acc[2*ks][1],0.f),   H.x, L.x);
        split_pack2(fmaxf(acc[2*ks][2],0.f),   fmaxf(acc[2*ks][3],0.f),   H.y, L.y);
        split_pack2(fmaxf(acc[2*ks+1][0],0.f), fmaxf(acc[2*ks+1][1],0.f), H.z, L.z);
        split_pack2(fmaxf(acc[2*ks+1][2],0.f), fmaxf(acc[2*ks+1][3],0.f), H.w, L.w);
        *(uint4*)(sp + a2h + ks*512 + lane*16) = H;
        *(uint4*)(sp + a2l + ks*512 + lane*16) = L;
    }
}

// =====================================================================
// FPS path (blocks 0-15). Bitwise-identical picks to reference.
// One barrier per iteration: warp shfl reduce -> lane0 stores packed u64
// key into double-buffered S[2][16]; after the barrier every thread scans
// the 16 keys itself (no atomics, no second barrier).
// =====================================================================
__device__ void fps_path(const float* __restrict__ pos, ull_t* S)
{
    const int b = blockIdx.x;
    const float* p = pos + (size_t)b * NP * 3;
    const int tid = threadIdx.x;
    const int wid = tid >> 5;
    const int lane = tid & 31;
    const int i0 = tid * 8;

    float px[8], py[8], pz[8], dmin[8];
    #pragma unroll
    for (int j = 0; j < 8; j++) {
        px[j] = p[3*(i0+j)+0];
        py[j] = p[3*(i0+j)+1];
        pz[j] = p[3*(i0+j)+2];
        dmin[j] = CUDART_INF_F;
    }

    if (tid == 0) {
        g_fps[b*SS] = 0;
        __threadfence();
        *(volatile int*)&g_prog[b] = 0;
    }
    __syncthreads();

    int cur = 0;
    for (int t = 1; t < SS; t++) {
        const float cx = p[3*cur], cy = p[3*cur+1], cz = p[3*cur+2];

        #pragma unroll
        for (int j = 0; j < 8; j++)
            dmin[j] = fminf(dmin[j], d2_ref(px[j]-cx, py[j]-cy, pz[j]-cz));

        // local argmax: value tree, then first index by equality
        float m01 = fmaxf(dmin[0], dmin[1]), m23 = fmaxf(dmin[2], dmin[3]);
        float m45 = fmaxf(dmin[4], dmin[5]), m67 = fmaxf(dmin[6], dmin[7]);
        float bv  = fmaxf(fmaxf(m01, m23), fmaxf(m45, m67));
        int bi = i0;
        #pragma unroll
        for (int j = 7; j >= 0; j--)
            if (dmin[j] == bv) bi = i0 + j;   // last assignment = smallest j

        // warp reduce (max value, min index on tie)
        #pragma unroll
        for (int o = 16; o > 0; o >>= 1) {
            float v2 = __shfl_down_sync(0xffffffffu, bv, o);
            int   i2 = __shfl_down_sync(0xffffffffu, bi, o);
            if (v2 > bv || (v2 == bv && i2 < bi)) { bv = v2; bi = i2; }
        }
        // double-buffered per-warp keys (WAR protected by the single barrier)
        ull_t* Sb = S + (t & 1)*16;
        if (lane == 0)
            Sb[wid] = ((ull_t)__float_as_uint(bv) << 32)
                    | (ull_t)(0xFFFFFFFFu - (uint_t)bi);
        __syncthreads();

        // every thread scans the 16 keys (broadcast LDS, tree max)
        ull_t k[16];
        #pragma unroll
        for (int w = 0; w < 16; w++) k[w] = Sb[w];
        #pragma unroll
        for (int s = 8; s > 0; s >>= 1)
            #pragma unroll
            for (int w = 0; w < 8; w++)
                if (w < s) k[w] = (k[w+s] > k[w]) ? k[w+s] : k[w];
        cur = (int)(0xFFFFFFFFu - (uint_t)(k[0] & 0xFFFFFFFFull));

        if (tid == 0) {
            g_fps[b*SS + t] = cur;
            if ((t & 3) == 3 || t == SS-1) {
                __threadfence();
                *(volatile int*)&g_prog[b] = t;
            }
        }
    }
}

// =====================================================================
// Fused kernel: blocks 0-15 FPS; blocks 16-147 presplit + ballq + MLP.
// Task order tracks the FPS frontier: cloud = task & 15, intra = task >> 4.
// =====================================================================
__global__ __launch_bounds__(512, 1) void fused_kernel(
    const float* __restrict__ x, const float* __restrict__ pos,
    const float* __restrict__ W1, const float* __restrict__ b1,
    const float* __restrict__ W2, const float* __restrict__ b2,
    const float* __restrict__ W3, const float* __restrict__ b3,
    float* __restrict__ out, long long out_size)
{
    extern __shared__ unsigned char sp[];
    const int tid = threadIdx.x;

    if (blockIdx.x < NB) {
        fps_path(pos, (ull_t*)sp);
        return;
    }

    // ------------------- worker block -------------------
    const int wb = blockIdx.x - NB;

    // presplit x chunk (strided over workers)
    {
        const int N4 = NB*NP*CIN/4;
        const float4* x4 = (const float4*)x;
        uint2* xh2 = (uint2*)g_xh;
        uint2* xl2 = (uint2*)g_xl;
        for (int i = wb*512 + tid; i < N4; i += NWORK*512) {
            float4 v = x4[i];
            ushort_t h0,l0,h1,l1,h2,l2,h3,l3;
            split_one(v.x,h0,l0); split_one(v.y,h1,l1);
            split_one(v.z,h2,l2); split_one(v.w,h3,l3);
            xh2[i] = make_uint2((uint_t)h0|((uint_t)h1<<16), (uint_t)h2|((uint_t)h3<<16));
            xl2[i] = make_uint2((uint_t)l0|((uint_t)l1<<16), (uint_t)l2|((uint_t)l3<<16));
        }
        __syncthreads();
        if (tid == 0) { __threadfence(); atomicAdd(&g_done, 1); }
    }

    float* bs = (float*)(sp + O_BIAS);

    // pack weights into fragment order (once per block)
    for (int i = tid; i < 136*32; i += 512) {
        const int s = i >> 5, l = i & 31;
        int ks, nt, layer;
        if (s < 40)      { layer = 1; ks = s >> 3;        nt = s & 7; }
        else if (s < 72) { layer = 2; ks = (s-40) >> 3;   nt = (s-40) & 7; }
        else             { layer = 3; ks = (s-72) >> 4;   nt = (s-72) & 15; }
        const int n  = nt*8 + (l >> 2);
        const int k0 = ks*16 + (l & 3)*2;
        float v[4];
        #pragma unroll
        for (int q = 0; q < 4; q++) {
            const int k = k0 + (q >> 1)*8 + (q & 1);
            if (layer == 1)      v[q] = (k < 67) ? W1[k*64 + n]  : 0.f;
            else if (layer == 2) v[q] = W2[k*64 + n];
            else                 v[q] = W3[k*128 + n];
        }
        uint2 H, L;
        split_pack2(v[0], v[1], H.x, L.x);
        split_pack2(v[2], v[3], H.y, L.y);
        ((uint2*)(sp + O_BH))[i] = H;
        ((uint2*)(sp + O_BL))[i] = L;
    }
    if (tid < 64)  { bs[tid] = b1[tid]; bs[64+tid] = b2[tid]; }
    if (tid < 128) { bs[128+tid] = b3[tid]; }
    __syncthreads();

    const int wid   = tid >> 5;
    const int lane  = tid & 31;
    const int team  = tid >> 7;
    const int t128  = tid & 127;
    const int wteam = t128 >> 5;
    const int g4    = lane >> 2;
    const int barid = team + 1;

    const int a1h_t = O_A1H + team*10240;
    const int a1l_t = O_A1L + team*10240;
    const int awh1  = a1h_t + wteam*2560;
    const int awl1  = a1l_t + wteam*2560;
    const int awh2  = O_A2H + team*8192 + wteam*2048;
    const int awl2  = O_A2L + team*8192 + wteam*2048;
    float* tred = (float*)(sp + O_RED) + team*256;

    ull_t* bqbuf = (ull_t*)(sp + O_A1H);         // 8 warps x 256 = 16KB (aliased)
    int*   scnt  = (int*)(sp + O_RED);           // aliased, phase-separated

    // wait for presplit completion (overlaps with first FPS iters)
    if (tid == 0) {
        volatile int* vd = &g_done;
        int guard = 0;
        while (*vd < NWORK && guard++ < SPIN_GUARD) __nanosleep(128);
        __threadfence();
    }
    __syncthreads();

    float acc[8][4];

    for (int task = wb; task < NTILE; task += NWORK) {
        const int cloudb = task & 15;                 // frontier-tracking order
        const int intra  = task >> 4;
        const int gbase  = cloudb*SS + intra*8;
        const int t_need = intra*8 + 7;

        // ---- gate on FPS progress ----
        if (tid == 0) {
            volatile int* vp = &g_prog[cloudb];
            int guard = 0;
            while (*vp < t_need && guard++ < SPIN_GUARD) __nanosleep(128);
            __threadfence();
        }
        __syncthreads();   // separates previous MLP's A-region use from ballq bufs

        // ---- ballq phase: warps 0-7, one center each ----
        if (wid < 8) {
            const int g = gbase + wid;
            const float* p = pos + (size_t)cloudb * NP * 3;
            const int ci = g_fps[g];
            const float cx = p[3*ci], cy = p[3*ci+1], cz = p[3*ci+2];
            ull_t* buf = bqbuf + wid*256;

            if (lane == 0) scnt[wid] = 0;
            __syncwarp();

            for (int i = lane; i < NP; i += 32) {
                float d = d2_ref(cx - p[3*i], cy - p[3*i+1], cz - p[3*i+2]);
                if (d <= 0.04f) {
                    int pp = atomicAdd(&scnt[wid], 1);
                    if (pp < 256)
                        buf[pp] = ((ull_t)__float_as_uint(d) << 32) | (uint_t)i;
                }
            }
            __syncwarp();
            const int m = min(scnt[wid], 256);

            if (m > KK) {
                const int n2 = (m <= 128) ? 128 : 256;
                for (int i = m + lane; i < n2; i += 32) buf[i] = ~0ull;
                __syncwarp();
                for (int k = 2; k <= n2; k <<= 1) {
                    for (int j = k >> 1; j > 0; j >>= 1) {
                        for (int i = lane; i < n2; i += 32) {
                            int ixj = i ^ j;
                            if (ixj > i) {
                                ull_t a = buf[i], c = buf[ixj];
                                bool up = ((i & k) == 0);
                                if ((a > c) == up) { buf[i] = c; buf[ixj] = a; }
                            }
                        }
                        __syncwarp();
                    }
                }
            }
            __syncwarp();

            const int n = min(m, KK);
            if (lane == 0) g_cnt[g] = n;
            for (int t = lane; t < KK; t += 32) {
                ull_t e = buf[(t < n) ? t : 0];
                g_nbr[g*KK + t] = (int)(e & 0xffffffffu);
            }

            // fused tail: pos_out + batch_out
            if (lane == 0) {
                const long long base = (long long)NC * 128;
                if (base + (long long)NC * 3 <= out_size) {
                    out[base + g*3 + 0] = cx;
                    out[base + g*3 + 1] = cy;
                    out[base + g*3 + 2] = cz;
                }
                const long long base2 = base + (long long)NC * 3;
                const long long rem = out_size - base2;
                if (rem >= (long long)NC * 2) {
                    ((long long*)(out + base2))[g] = (long long)cloudb;
                } else if (rem >= (long long)NC) {
                    out[base2 + g] = (float)cloudb;
                }
            }
        }
        __syncthreads();   // all bqbuf reads done

        // ---- re-zero ks=4 padding blocks (clobbered by bqbuf aliasing) ----
        for (int i = tid; i < 1024; i += 512) {
            const int tm = i >> 8, w = (i >> 6) & 3, hl = (i >> 5) & 1, l = i & 31;
            const int base = (hl ? O_A1L : O_A1H) + tm*10240 + w*2560 + 4*512 + l*16;
            *(uint4*)(sp + base) = make_uint4(0,0,0,0);
        }
        __syncthreads();   // zeros visible before gather writes rel-pos

        // ---- MLP phase: 4 teams x 2 rounds = 8 centers ----
        #pragma unroll 1
        for (int r = 0; r < 2; r++) {
            const int g = gbase + team*2 + r;
            const float* p = pos + (size_t)cloudb * NP * 3;
            const int ci = g_fps[g];
            const int ncnt = g_cnt[g];

            // gather into fragment-packed A1
            {
                const int rr = t128 >> 1, half = t128 & 1;
                const int idx = g_nbr[g*KK + rr];
                const size_t row = (size_t)(cloudb*NP + idx);
                const uint4* xh4 = (const uint4*)(g_xh + row*CIN);
                const uint4* xl4 = (const uint4*)(g_xl + row*CIN);
                const int dw   = rr >> 4;
                const int lb   = 4*(rr & 7);
                const int rhi  = ((rr & 15) >= 8) ? 1 : 0;
                const int bh_w = a1h_t + dw*2560;
                const int bl_w = a1l_t + dw*2560;
                #pragma unroll
                for (int q = 0; q < 4; q++) {
                    const uint4 vh = xh4[4*half + q];
                    const uint4 vl = xl4[4*half + q];
                    const int ks  = 2*half + (q >> 1);
                    const int reg = ((q & 1) << 1) + rhi;
                    const int bh  = bh_w + ks*512 + reg*4;
                    const int bl  = bl_w + ks*512 + reg*4;
                    *(uint_t*)(sp + bh + (lb+0)*16) = vh.x;
                    *(uint_t*)(sp + bh + (lb+1)*16) = vh.y;
                    *(uint_t*)(sp + bh + (lb+2)*16) = vh.z;
                    *(uint_t*)(sp + bh + (lb+3)*16) = vh.w;
                    *(uint_t*)(sp + bl + (lb+0)*16) = vl.x;
                    *(uint_t*)(sp + bl + (lb+1)*16) = vl.y;
                    *(uint_t*)(sp + bl + (lb+2)*16) = vl.z;
                    *(uint_t*)(sp + bl + (lb+3)*16) = vl.w;
                }
                // ks=4 block: rel-pos only (padding pre-zeroed; same two slots
                // rewritten every round -> no race, no staleness)
                if (half == 0) {
                    const float rx = p[3*idx]   - p[3*ci];
                    const float ry = p[3*idx+1] - p[3*ci+1];
                    const float rz = p[3*idx+2] - p[3*ci+2];
                    uint_t h0,l0,h1,l1;
                    split_pack2(rx, ry, h0, l0);
                    split_pack2(rz, 0.f, h1, l1);
                    const int bh = bh_w + 4*512 + rhi*4;
                    const int bl = bl_w + 4*512 + rhi*4;
                    *(uint_t*)(sp + bh + (lb+0)*16) = h0;
                    *(uint_t*)(sp + bh + (lb+1)*16) = h1;
                    *(uint_t*)(sp + bl + (lb+0)*16) = l0;
                    *(uint_t*)(sp + bl + (lb+1)*16) = l1;
                }
            }
            asm volatile("bar.sync %0, %1;" :: "r"(barid), "r"(128));

            // layer 1
            mm_packed<5,8>(sp, awh1, awl1, SLOT_L1, 0, bs, acc, lane);
            epi_relu_pack(sp, awh2, awl2, acc, lane);
            asm volatile("bar.sync %0, %1;" :: "r"(barid), "r"(128));

            // layer 2 (in place)
            mm_packed<4,8>(sp, awh2, awl2, SLOT_L2, 0, bs+64, acc, lane);
            asm volatile("bar.sync %0, %1;" :: "r"(barid), "r"(128));
            epi_relu_pack(sp, awh2, awl2, acc, lane);
            asm volatile("bar.sync %0, %1;" :: "r"(barid), "r"(128));

            // layer 3 + masked column max
            const bool v0 = g4     < ncnt - wteam*16;
            const bool v1 = g4 + 8 < ncnt - wteam*16;
            #pragma unroll
            for (int h = 0; h < 2; h++) {
                mm_packed<4,16>(sp, awh2, awl2, SLOT_L3, h*8, bs+128+h*64, acc, lane);
                #pragma unroll
                for (int nt = 0; nt < 8; nt++) {
                    float m0 = fmaxf(v0 ? acc[nt][0] : -CUDART_INF_F,
                                     v1 ? acc[nt][2] : -CUDART_INF_F);
                    float m1 = fmaxf(v0 ? acc[nt][1] : -CUDART_INF_F,
                                     v1 ? acc[nt][3] : -CUDART_INF_F);
                    #pragma unroll
                    for (int off = 4; off < 32; off <<= 1) {
                        m0 = fmaxf(m0, __shfl_xor_sync(0xffffffffu, m0, off));
                        m1 = fmaxf(m1, __shfl_xor_sync(0xffffffffu, m1, off));
                    }
                    if (lane < 4) {
                        tred[wteam*64 + nt*8 + lane*2    ] = m0;
                        tred[wteam*64 + nt*8 + lane*2 + 1] = m1;
                    }
                }
                asm volatile("bar.sync %0, %1;" :: "r"(barid), "r"(128));
                if (t128 < 64) {
                    float m = fmaxf(fmaxf(tred[t128], tred[64+t128]),
                                    fmaxf(tred[128+t128], tred[192+t128]));
                    out[(size_t)g*128 + h*64 + t128] = m;
                }
                asm volatile("bar.sync %0, %1;" :: "r"(barid), "r"(128));
            }
        }
    }
}

// =====================================================================
extern "C" void kernel_launch(void* const* d_in, const int* in_sizes, int n_in,
                              void* d_out, int out_size)
{
    const float* x   = (const float*)d_in[0];
    const float* pos = (const float*)d_in[1];
    const float* W1 = (const float*)d_in[3];
    const float* b1 = (const float*)d_in[4];
    const float* W2 = (const float*)d_in[5];
    const float* b2 = (const float*)d_in[6];
    const float* W3 = (const float*)d_in[7];
    const float* b3 = (const float*)d_in[8];
    float* out = (float*)d_out;

    cudaFuncSetAttribute(fused_kernel, cudaFuncAttributeMaxDynamicSharedMemorySize, SMEM_TOTAL);

    init_kernel<<<1, 32>>>();
    fused_kernel<<<148, 512, SMEM_TOTAL>>>(x, pos, W1, b1, W2, b2, W3, b3,
                                           out, (long long)out_size);
}

// round 11
// speedup vs baseline: 1.7673x; 1.6263x over previous
#include <cuda_runtime.h>
#include <cuda_bf16.h>
#include <math_constants.h>

#define NB   16
#define NP   4096
#define SS   1024
#define KK   64
#define CIN  64
#define NC   (NB*SS)   /* 16384 centers */
#define NWORK 132      /* worker blocks */
#define NTILE 2048     /* 8-center tasks */
#define SPIN_GUARD (1<<24)

typedef unsigned short ushort_t;
typedef unsigned int   uint_t;
typedef unsigned long long ull_t;

// ---------------- scratch (static device globals; no allocation) ----------------
__device__ int g_fps[NC];
__device__ int g_nbr[NC*KK];
__device__ int g_cnt[NC];
__device__ int g_prog[NB];
__device__ int g_done;
__device__ ushort_t g_xh[(size_t)NB*NP*CIN];   // pre-split x, hi bf16
__device__ ushort_t g_xl[(size_t)NB*NP*CIN];   // pre-split x, lo bf16

// Reference-matching squared distance: no FMA contraction, sum order (x+y)+z.
__device__ __forceinline__ float d2_ref(float dx, float dy, float dz) {
    return __fadd_rn(__fadd_rn(__fmul_rn(dx,dx), __fmul_rn(dy,dy)), __fmul_rn(dz,dz));
}

__device__ __forceinline__ void split_one(float v, ushort_t& h, ushort_t& l) {
    __nv_bfloat16 hb = __float2bfloat16(v);
    __nv_bfloat16 lb = __float2bfloat16(v - __bfloat162float(hb));
    h = __bfloat16_as_ushort(hb); l = __bfloat16_as_ushort(lb);
}
__device__ __forceinline__ void split_pack2(float a, float b, uint_t& h, uint_t& l) {
    ushort_t ha, la, hb, lb;
    split_one(a, ha, la); split_one(b, hb, lb);
    h = (uint_t)ha | ((uint_t)hb << 16);
    l = (uint_t)la | ((uint_t)lb << 16);
}
__device__ __forceinline__ void mma16816(float* c, uint_t a0,uint_t a1,uint_t a2,uint_t a3,
                                         uint_t b0, uint_t b1) {
    asm volatile("mma.sync.aligned.m16n8k16.row.col.f32.bf16.bf16.f32 "
        "{%0,%1,%2,%3}, {%4,%5,%6,%7}, {%8,%9}, {%0,%1,%2,%3};"
        : "+f"(c[0]),"+f"(c[1]),"+f"(c[2]),"+f"(c[3])
        : "r"(a0),"r"(a1),"r"(a2),"r"(a3),"r"(b0),"r"(b1));
}

// =====================================================================
// init: reset cross-launch state (tiny, runs before fused kernel)
// =====================================================================
__global__ void init_kernel()
{
    if (threadIdx.x < NB) g_prog[threadIdx.x] = -1;
    if (threadIdx.x == 0) g_done = 0;
}

// =====================================================================
// smem layout (byte offsets) — worker path
// =====================================================================
#define O_BIAS 0
#define O_BH   1024
#define O_BL   35840
#define O_A1H  70656
#define O_A1L  111616
#define O_A2H  152576
#define O_A2L  185344
#define O_RED  218112
#define SMEM_TOTAL 222208
#define SLOT_L1 0
#define SLOT_L2 40
#define SLOT_L3 72

template<int KS, int NTL>
__device__ __forceinline__ void mm_packed(
    const unsigned char* sp, int awh, int awl, int slotbase, int ntofs,
    const float* __restrict__ bsl, float acc[8][4], int lane)
{
    const int tig = lane & 3;
    #pragma unroll
    for (int nt = 0; nt < 8; nt++) {
        const int c0 = nt*8 + tig*2;
        acc[nt][0] = bsl[c0]; acc[nt][1] = bsl[c0+1];
        acc[nt][2] = acc[nt][0]; acc[nt][3] = acc[nt][1];
    }
    const uint2* BH = (const uint2*)(sp + O_BH);
    const uint2* BL = (const uint2*)(sp + O_BL);
    #pragma unroll
    for (int ks = 0; ks < KS; ks++) {
        const uint4 Ah = *(const uint4*)(sp + awh + ks*512 + lane*16);
        const uint4 Al = *(const uint4*)(sp + awl + ks*512 + lane*16);
        #pragma unroll
        for (int nt = 0; nt < 8; nt++) {
            const int slot = (slotbase + ks*NTL + ntofs + nt)*32 + lane;
            const uint2 bh = BH[slot];
            const uint2 bl = BL[slot];
            mma16816(acc[nt], Ah.x,Ah.y,Ah.z,Ah.w, bh.x,bh.y);
            mma16816(acc[nt], Ah.x,Ah.y,Ah.z,Ah.w, bl.x,bl.y);
            mma16816(acc[nt], Al.x,Al.y,Al.z,Al.w, bh.x,bh.y);
        }
    }
}

__device__ __forceinline__ void epi_relu_pack(
    unsigned char* sp, int a2h, int a2l, float acc[8][4], int lane)
{
    #pragma unroll
    for (int ks = 0; ks < 4; ks++) {
        uint4 H, L;
        split_pack2(fmaxf(acc[2*ks][0],0.f),   fmaxf(acc[2*ks][1],0.f),   H.x, L.x);
        split_pack2(fmaxf(acc[2*ks][2],0.f),   fmaxf(acc[2*ks][3],0.f),   H.y, L.y);
        split_pack2(fmaxf(acc[2*ks+1][0],0.f), fmaxf(acc[2*ks+1][1],0.f), H.z, L.z);
        split_pack2(fmaxf(acc[2*ks+1][2],0.f), fmaxf(acc[2*ks+1][3],0.f), H.w, L.w);
        *(uint4*)(sp + a2h + ks*512 + lane*16) = H;
        *(uint4*)(sp + a2l + ks*512 + lane*16) = L;
    }
}

// =====================================================================
// FPS path (blocks 0-15). Bitwise-identical picks to reference.
// pos cached in smem (no global loads in the loop). Reduction:
// warp shfl -> 16 keys in smem -> warp0 16-lane shfl reduce. 2 barriers.
// =====================================================================
__device__ void fps_path(const float* __restrict__ pos, unsigned char* sp)
{
    float* spos = (float*)sp;                    // 48KB pos cache
    ull_t* S    = (ull_t*)(sp + 49152);          // 16 per-warp keys
    volatile int* scur = (int*)(sp + 49152 + 128);

    const int b = blockIdx.x;
    const float* p = pos + (size_t)b * NP * 3;
    const int tid  = threadIdx.x;
    const int wid  = tid >> 5;
    const int lane = tid & 31;
    const int i0 = tid * 8;

    // cache cloud positions in smem (3072 float4)
    {
        const float4* p4 = (const float4*)p;
        float4* s4 = (float4*)spos;
        for (int i = tid; i < NP*3/4; i += 512) s4[i] = p4[i];
    }
    if (tid == 0) {
        g_fps[b*SS] = 0;
        __threadfence();
        *(volatile int*)&g_prog[b] = 0;
    }
    __syncthreads();

    float px[8], py[8], pz[8], dmin[8];
    #pragma unroll
    for (int j = 0; j < 8; j++) {
        px[j] = spos[3*(i0+j)+0];
        py[j] = spos[3*(i0+j)+1];
        pz[j] = spos[3*(i0+j)+2];
        dmin[j] = CUDART_INF_F;
    }

    int cur = 0;
    for (int t = 1; t < SS; t++) {
        const float cx = spos[3*cur], cy = spos[3*cur+1], cz = spos[3*cur+2];

        float bv = -1.0f; int bi = NP;
        #pragma unroll
        for (int j = 0; j < 8; j++) {
            float d  = d2_ref(px[j]-cx, py[j]-cy, pz[j]-cz);
            float dm = fminf(dmin[j], d);
            dmin[j] = dm;
            if (dm > bv) { bv = dm; bi = i0 + j; }   // strict > keeps first index
        }
        // warp reduce (max value, min index on tie)
        #pragma unroll
        for (int o = 16; o > 0; o >>= 1) {
            float v2 = __shfl_down_sync(0xffffffffu, bv, o);
            int   i2 = __shfl_down_sync(0xffffffffu, bi, o);
            if (v2 > bv || (v2 == bv && i2 < bi)) { bv = v2; bi = i2; }
        }
        if (lane == 0)
            S[wid] = ((ull_t)__float_as_uint(bv) << 32)
                   | (ull_t)(0xFFFFFFFFu - (uint_t)bi);
        __syncthreads();

        if (tid < 32) {
            ull_t k = (lane < 16) ? S[lane] : 0ull;
            #pragma unroll
            for (int o = 8; o > 0; o >>= 1) {
                ull_t k2 = __shfl_down_sync(0xffffffffu, k, o);
                if (k2 > k) k = k2;
            }
            if (lane == 0) {
                const int c = (int)(0xFFFFFFFFu - (uint_t)(k & 0xFFFFFFFFull));
                scur[0] = c;
                g_fps[b*SS + t] = c;
                if ((t & 3) == 3 || t == SS-1) {
                    __threadfence();
                    *(volatile int*)&g_prog[b] = t;
                }
            }
        }
        __syncthreads();
        cur = scur[0];
    }
}

// =====================================================================
// Fused kernel: blocks 0-15 FPS; blocks 16-147 presplit + ballq + MLP.
// Task order tracks the FPS frontier: cloud = task & 15, intra = task >> 4.
// =====================================================================
__global__ __launch_bounds__(512, 1) void fused_kernel(
    const float* __restrict__ x, const float* __restrict__ pos,
    const float* __restrict__ W1, const float* __restrict__ b1,
    const float* __restrict__ W2, const float* __restrict__ b2,
    const float* __restrict__ W3, const float* __restrict__ b3,
    float* __restrict__ out, long long out_size)
{
    extern __shared__ unsigned char sp[];
    const int tid = threadIdx.x;

    if (blockIdx.x < NB) {
        fps_path(pos, sp);
        return;
    }

    // ------------------- worker block -------------------
    const int wb = blockIdx.x - NB;

    // presplit x chunk (strided over workers)
    {
        const int N4 = NB*NP*CIN/4;
        const float4* x4 = (const float4*)x;
        uint2* xh2 = (uint2*)g_xh;
        uint2* xl2 = (uint2*)g_xl;
        for (int i = wb*512 + tid; i < N4; i += NWORK*512) {
            float4 v = x4[i];
            ushort_t h0,l0,h1,l1,h2,l2,h3,l3;
            split_one(v.x,h0,l0); split_one(v.y,h1,l1);
            split_one(v.z,h2,l2); split_one(v.w,h3,l3);
            xh2[i] = make_uint2((uint_t)h0|((uint_t)h1<<16), (uint_t)h2|((uint_t)h3<<16));
            xl2[i] = make_uint2((uint_t)l0|((uint_t)l1<<16), (uint_t)l2|((uint_t)l3<<16));
        }
        __syncthreads();
        if (tid == 0) { __threadfence(); atomicAdd(&g_done, 1); }
    }

    float* bs = (float*)(sp + O_BIAS);

    // pack weights into fragment order (once per block)
    for (int i = tid; i < 136*32; i += 512) {
        const int s = i >> 5, l = i & 31;
        int ks, nt, layer;
        if (s < 40)      { layer = 1; ks = s >> 3;        nt = s & 7; }
        else if (s < 72) { layer = 2; ks = (s-40) >> 3;   nt = (s-40) & 7; }
        else             { layer = 3; ks = (s-72) >> 4;   nt = (s-72) & 15; }
        const int n  = nt*8 + (l >> 2);
        const int k0 = ks*16 + (l & 3)*2;
        float v[4];
        #pragma unroll
        for (int q = 0; q < 4; q++) {
            const int k = k0 + (q >> 1)*8 + (q & 1);
            if (layer == 1)      v[q] = (k < 67) ? W1[k*64 + n]  : 0.f;
            else if (layer == 2) v[q] = W2[k*64 + n];
            else                 v[q] = W3[k*128 + n];
        }
        uint2 H, L;
        split_pack2(v[0], v[1], H.x, L.x);
        split_pack2(v[2], v[3], H.y, L.y);
        ((uint2*)(sp + O_BH))[i] = H;
        ((uint2*)(sp + O_BL))[i] = L;
    }
    if (tid < 64)  { bs[tid] = b1[tid]; bs[64+tid] = b2[tid]; }
    if (tid < 128) { bs[128+tid] = b3[tid]; }
    __syncthreads();

    const int wid   = tid >> 5;
    const int lane  = tid & 31;
    const int team  = tid >> 7;
    const int t128  = tid & 127;
    const int wteam = t128 >> 5;
    const int g4    = lane >> 2;
    const int barid = team + 1;

    const int a1h_t = O_A1H + team*10240;
    const int a1l_t = O_A1L + team*10240;
    const int awh1  = a1h_t + wteam*2560;
    const int awl1  = a1l_t + wteam*2560;
    const int awh2  = O_A2H + team*8192 + wteam*2048;
    const int awl2  = O_A2L + team*8192 + wteam*2048;
    float* tred = (float*)(sp + O_RED) + team*256;

    ull_t* bqbuf = (ull_t*)(sp + O_A1H);         // 8 warps x 256 = 16KB (aliased)
    int*   scnt  = (int*)(sp + O_RED);           // aliased, phase-separated

    // wait for presplit completion (overlaps with first FPS iters)
    if (tid == 0) {
        volatile int* vd = &g_done;
        int guard = 0;
        while (*vd < NWORK && guard++ < SPIN_GUARD) __nanosleep(128);
        __threadfence();
    }
    __syncthreads();

    float acc[8][4];

    for (int task = wb; task < NTILE; task += NWORK) {
        const int cloudb = task & 15;                 // frontier-tracking order
        const int intra  = task >> 4;
        const int gbase  = cloudb*SS + intra*8;
        const int t_need = intra*8 + 7;

        // ---- gate on FPS progress ----
        if (tid == 0) {
            volatile int* vp = &g_prog[cloudb];
            int guard = 0;
            while (*vp < t_need && guard++ < SPIN_GUARD) __nanosleep(128);
            __threadfence();
        }
        __syncthreads();   // separates previous MLP's A-region use from ballq bufs

        // ---- ballq phase: warps 0-7, one center each ----
        if (wid < 8) {
            const int g = gbase + wid;
            const float* p = pos + (size_t)cloudb * NP * 3;
            const int ci = g_fps[g];
            const float cx = p[3*ci], cy = p[3*ci+1], cz = p[3*ci+2];
            ull_t* buf = bqbuf + wid*256;

            if (lane == 0) scnt[wid] = 0;
            __syncwarp();

            for (int i = lane; i < NP; i += 32) {
                float d = d2_ref(cx - p[3*i], cy - p[3*i+1], cz - p[3*i+2]);
                if (d <= 0.04f) {
                    int pp = atomicAdd(&scnt[wid], 1);
                    if (pp < 256)
                        buf[pp] = ((ull_t)__float_as_uint(d) << 32) | (uint_t)i;
                }
            }
            __syncwarp();
            const int m = min(scnt[wid], 256);

            if (m > KK) {
                const int n2 = (m <= 128) ? 128 : 256;
                for (int i = m + lane; i < n2; i += 32) buf[i] = ~0ull;
                __syncwarp();
                for (int k = 2; k <= n2; k <<= 1) {
                    for (int j = k >> 1; j > 0; j >>= 1) {
                        for (int i = lane; i < n2; i += 32) {
                            int ixj = i ^ j;
                            if (ixj > i) {
                                ull_t a = buf[i], c = buf[ixj];
                                bool up = ((i & k) == 0);
                                if ((a > c) == up) { buf[i] = c; buf[ixj] = a; }
                            }
                        }
                        __syncwarp();
                    }
                }
            }
            __syncwarp();

            const int n = min(m, KK);
            if (lane == 0) g_cnt[g] = n;
            for (int t = lane; t < KK; t += 32) {
                ull_t e = buf[(t < n) ? t : 0];
                g_nbr[g*KK + t] = (int)(e & 0xffffffffu);
            }

            // fused tail: pos_out + batch_out
            if (lane == 0) {
                const long long base = (long long)NC * 128;
                if (base + (long long)NC * 3 <= out_size) {
                    out[base + g*3 + 0] = cx;
                    out[base + g*3 + 1] = cy;
                    out[base + g*3 + 2] = cz;
                }
                const long long base2 = base + (long long)NC * 3;
                const long long rem = out_size - base2;
                if (rem >= (long long)NC * 2) {
                    ((long long*)(out + base2))[g] = (long long)cloudb;
                } else if (rem >= (long long)NC) {
                    out[base2 + g] = (float)cloudb;
                }
            }
        }
        __syncthreads();   // all bqbuf reads done

        // ---- re-zero ks=4 padding blocks (clobbered by bqbuf aliasing) ----
        for (int i = tid; i < 1024; i += 512) {
            const int tm = i >> 8, w = (i >> 6) & 3, hl = (i >> 5) & 1, l = i & 31;
            const int base = (hl ? O_A1L : O_A1H) + tm*10240 + w*2560 + 4*512 + l*16;
            *(uint4*)(sp + base) = make_uint4(0,0,0,0);
        }
        __syncthreads();   // zeros visible before gather writes rel-pos

        // ---- MLP phase: 4 teams x 2 rounds = 8 centers ----
        #pragma unroll 1
        for (int r = 0; r < 2; r++) {
            const int g = gbase + team*2 + r;
            const float* p = pos + (size_t)cloudb * NP * 3;
            const int ci = g_fps[g];
            const int ncnt = g_cnt[g];

            // gather into fragment-packed A1
            {
                const int rr = t128 >> 1, half = t128 & 1;
                const int idx = g_nbr[g*KK + rr];
                const size_t row = (size_t)(cloudb*NP + idx);
                const uint4* xh4 = (const uint4*)(g_xh + row*CIN);
                const uint4* xl4 = (const uint4*)(g_xl + row*CIN);
                const int dw   = rr >> 4;
                const int lb   = 4*(rr & 7);
                const int rhi  = ((rr & 15) >= 8) ? 1 : 0;
                const int bh_w = a1h_t + dw*2560;
                const int bl_w = a1l_t + dw*2560;
                #pragma unroll
                for (int q = 0; q < 4; q++) {
                    const uint4 vh = xh4[4*half + q];
                    const uint4 vl = xl4[4*half + q];
                    const int ks  = 2*half + (q >> 1);
                    const int reg = ((q & 1) << 1) + rhi;
                    const int bh  = bh_w + ks*512 + reg*4;
                    const int bl  = bl_w + ks*512 + reg*4;
                    *(uint_t*)(sp + bh + (lb+0)*16) = vh.x;
                    *(uint_t*)(sp + bh + (lb+1)*16) = vh.y;
                    *(uint_t*)(sp + bh + (lb+2)*16) = vh.z;
                    *(uint_t*)(sp + bh + (lb+3)*16) = vh.w;
                    *(uint_t*)(sp + bl + (lb+0)*16) = vl.x;
                    *(uint_t*)(sp + bl + (lb+1)*16) = vl.y;
                    *(uint_t*)(sp + bl + (lb+2)*16) = vl.z;
                    *(uint_t*)(sp + bl + (lb+3)*16) = vl.w;
                }
                // ks=4 block: rel-pos only (padding pre-zeroed; same two slots
                // rewritten every round -> no race, no staleness)
                if (half == 0) {
                    const float rx = p[3*idx]   - p[3*ci];
                    const float ry = p[3*idx+1] - p[3*ci+1];
                    const float rz = p[3*idx+2] - p[3*ci+2];
                    uint_t h0,l0,h1,l1;
                    split_pack2(rx, ry, h0, l0);
                    split_pack2(rz, 0.f, h1, l1);
                    const int bh = bh_w + 4*512 + rhi*4;
                    const int bl = bl_w + 4*512 + rhi*4;
                    *(uint_t*)(sp + bh + (lb+0)*16) = h0;
                    *(uint_t*)(sp + bh + (lb+1)*16) = h1;
                    *(uint_t*)(sp + bl + (lb+0)*16) = l0;
                    *(uint_t*)(sp + bl + (lb+1)*16) = l1;
                }
            }
            asm volatile("bar.sync %0, %1;" :: "r"(barid), "r"(128));

            // layer 1
            mm_packed<5,8>(sp, awh1, awl1, SLOT_L1, 0, bs, acc, lane);
            epi_relu_pack(sp, awh2, awl2, acc, lane);
            asm volatile("bar.sync %0, %1;" :: "r"(barid), "r"(128));

            // layer 2 (in place)
            mm_packed<4,8>(sp, awh2, awl2, SLOT_L2, 0, bs+64, acc, lane);
            asm volatile("bar.sync %0, %1;" :: "r"(barid), "r"(128));
            epi_relu_pack(sp, awh2, awl2, acc, lane);
            asm volatile("bar.sync %0, %1;" :: "r"(barid), "r"(128));

            // layer 3 + masked column max
            const bool v0 = g4     < ncnt - wteam*16;
            const bool v1 = g4 + 8 < ncnt - wteam*16;
            #pragma unroll
            for (int h = 0; h < 2; h++) {
                mm_packed<4,16>(sp, awh2, awl2, SLOT_L3, h*8, bs+128+h*64, acc, lane);
                #pragma unroll
                for (int nt = 0; nt < 8; nt++) {
                    float m0 = fmaxf(v0 ? acc[nt][0] : -CUDART_INF_F,
                                     v1 ? acc[nt][2] : -CUDART_INF_F);
                    float m1 = fmaxf(v0 ? acc[nt][1] : -CUDART_INF_F,
                                     v1 ? acc[nt][3] : -CUDART_INF_F);
                    #pragma unroll
                    for (int off = 4; off < 32; off <<= 1) {
                        m0 = fmaxf(m0, __shfl_xor_sync(0xffffffffu, m0, off));
                        m1 = fmaxf(m1, __shfl_xor_sync(0xffffffffu, m1, off));
                    }
                    if (lane < 4) {
                        tred[wteam*64 + nt*8 + lane*2    ] = m0;
                        tred[wteam*64 + nt*8 + lane*2 + 1] = m1;
                    }
                }
                asm volatile("bar.sync %0, %1;" :: "r"(barid), "r"(128));
                if (t128 < 64) {
                    float m = fmaxf(fmaxf(tred[t128], tred[64+t128]),
                                    fmaxf(tred[128+t128], tred[192+t128]));
                    out[(size_t)g*128 + h*64 + t128] = m;
                }
                asm volatile("bar.sync %0, %1;" :: "r"(barid), "r"(128));
            }
        }
    }
}

// =====================================================================
extern "C" void kernel_launch(void* const* d_in, const int* in_sizes, int n_in,
                              void* d_out, int out_size)
{
    const float* x   = (const float*)d_in[0];
    const float* pos = (const float*)d_in[1];
    const float* W1 = (const float*)d_in[3];
    const float* b1 = (const float*)d_in[4];
    const float* W2 = (const float*)d_in[5];
    const float* b2 = (const float*)d_in[6];
    const float* W3 = (const float*)d_in[7];
    const float* b3 = (const float*)d_in[8];
    float* out = (float*)d_out;

    cudaFuncSetAttribute(fused_kernel, cudaFuncAttributeMaxDynamicSharedMemorySize, SMEM_TOTAL);

    init_kernel<<<1, 32>>>();
    fused_kernel<<<148, 512, SMEM_TOTAL>>>(x, pos, W1, b1, W2, b2, W3, b3,
                                           out, (long long)out_size);
}